// round 6
// baseline (speedup 1.0000x reference)
#include <cuda_runtime.h>

#define MDIM 1024
#define GR   16                 // rows per block = warps per block
#define TPB  512
#define ROWSTRIDE (3*MDIM)      // [x(1024) | pp interleaved(2048)]

// shared layout: row buffers | schedule (short4) | weights | epi weights | offsets
#define BUF_BYTES  (GR*ROWSTRIDE*4)            // 196608
#define SIDX_OFF   (BUF_BYTES)                 // short4[M] remapped parents     8192
#define SWT_OFF    (SIDX_OFF + MDIM*8)         // float4[M] (w0',w1',b',-)      16384
#define WEPI_OFF   (SWT_OFF  + MDIM*16)        // float2[M] (wp',wq') permuted   8192
#define OFFS_OFF   (WEPI_OFF + MDIM*8)         // short[1026] level offsets      2056
#define SMEM_BYTES (OFFS_OFF + 2056)           // 231432 <= 232448 cap

__device__ __forceinline__ float sigmoid_fold(float t) {   // t = -z*log2e
    float e, p;
    asm("ex2.approx.f32 %0, %1;" : "=f"(e) : "f"(t));
    asm("rcp.approx.f32 %0, %1;" : "=f"(p) : "f"(1.0f + e));
    return p;
}

// ---------------------------------------------------------------------------
// Fused kernel. Per-block setup builds a level-sorted schedule with step ids
// remapped so (a) stores are contiguous and (b) plus/prod interleave as one
// float2 per step: enc(x,c)=c, enc(plus,s)=M+2*pos[s], enc(prod,s)=M+2*pos[s]+1.
// Main: one WARP owns one row in smem; zero block-wide barriers after setup;
// per-level __syncwarp; next level's schedule prefetched AND unpacked to int
// registers before the sync (off the dependent chain).
// ---------------------------------------------------------------------------
__global__ void __launch_bounds__(TPB, 1)
tree_kernel(const float* __restrict__ x,      const int* __restrict__ raw,
            const float* __restrict__ W_base, const float* __restrict__ b_base,
            const float* __restrict__ W_sig,  const float* __restrict__ b_sig,
            const float* __restrict__ w_plus, const float* __restrict__ b_plus,
            const float* __restrict__ w_prod, const float* __restrict__ b_prod,
            float* __restrict__ out, int nGroups)
{
    extern __shared__ char smraw[];
    float*  buf  = (float*) smraw;                       // [GR][3*M]
    short4* sIdx = (short4*)(smraw + SIDX_OFF);
    float4* sWt  = (float4*)(smraw + SWT_OFF);
    float2* wepi = (float2*)(smraw + WEPI_OFF);
    short*  offs = (short*) (smraw + OFFS_OFF);

    // setup scratch overlaid on buf (released before staging rows)
    short4* sP   = (short4*)smraw;                       // [M] raw parents
    int*    lvl  = (int*)(smraw + 8192);
    int*    cnt  = (int*)(smraw + 12288);
    int*    cur  = (int*)(smraw + 16384);
    int*    posA = (int*)(smraw + 20480);

    int tid  = threadIdx.x;
    int lane = tid & 31;
    int wid  = tid >> 5;

    // ---- Phase 0: stage parents, zero counters ----------------------------
    for (int i = tid; i < MDIM; i += TPB) {
        short4 p;
        p.x = (short)raw[2*i];          p.y = (short)raw[2*i + 1];
        p.z = (short)raw[2*MDIM + 2*i]; p.w = (short)raw[2*MDIM + 2*i + 1];
        sP[i] = p;
        cnt[i] = 0;
    }
    __syncthreads();

    // ---- Phase 1: exact DAG levels, warp 0 over 32-step chunks ------------
    if (wid == 0) {
        for (int c = 0; c < MDIM/32; c++) {
            int idx  = c*32 + lane;
            int base = c*32;
            short4 p = sP[idx];
            int l = 0;
            int e0 = -1, e1 = -1, e2 = -1, e3 = -1;
            int q;
            q = p.x; if (q >= MDIM) { int pc = q & (MDIM-1); if (pc < base) l = max(l, lvl[pc]+1); else e0 = pc - base; }
            q = p.y; if (q >= MDIM) { int pc = q & (MDIM-1); if (pc < base) l = max(l, lvl[pc]+1); else e1 = pc - base; }
            q = p.z; if (q >= MDIM) { int pc = q & (MDIM-1); if (pc < base) l = max(l, lvl[pc]+1); else e2 = pc - base; }
            q = p.w; if (q >= MDIM) { int pc = q & (MDIM-1); if (pc < base) l = max(l, lvl[pc]+1); else e3 = pc - base; }
            for (;;) {
                int v0 = __shfl_sync(0xffffffffu, l, e0 < 0 ? 0 : e0);
                int v1 = __shfl_sync(0xffffffffu, l, e1 < 0 ? 0 : e1);
                int v2 = __shfl_sync(0xffffffffu, l, e2 < 0 ? 0 : e2);
                int v3 = __shfl_sync(0xffffffffu, l, e3 < 0 ? 0 : e3);
                int nl = l;
                if (e0 >= 0) nl = max(nl, v0 + 1);
                if (e1 >= 0) nl = max(nl, v1 + 1);
                if (e2 >= 0) nl = max(nl, v2 + 1);
                if (e3 >= 0) nl = max(nl, v3 + 1);
                unsigned ch = __ballot_sync(0xffffffffu, nl != l);
                l = nl;
                if (!ch) break;
            }
            lvl[idx] = l;
        }
    }
    __syncthreads();

    // ---- Phase 2: level histogram -----------------------------------------
    for (int i = tid; i < MDIM; i += TPB) atomicAdd(&cnt[lvl[i]], 1);
    __syncthreads();

    // ---- Phase 3: warp-0 scan -> level offsets ----------------------------
    if (wid == 0) {
        int carry = 0;
        for (int b = 0; b < MDIM; b += 32) {
            int v = cnt[b + lane];
            int s = v;
            #pragma unroll
            for (int o = 1; o < 32; o <<= 1) {
                int t = __shfl_up_sync(0xffffffffu, s, o);
                if (lane >= o) s += t;
            }
            int excl = carry + s - v;
            offs[b + lane] = (short)excl;
            cur[b + lane]  = excl;
            carry += __shfl_sync(0xffffffffu, s, 31);
        }
        if (lane == 0) { offs[MDIM] = MDIM; offs[MDIM+1] = MDIM; }
    }
    __syncthreads();

    // ---- Phase 4: schedule position of every step -------------------------
    for (int i = tid; i < MDIM; i += TPB) posA[i] = atomicAdd(&cur[lvl[i]], 1);
    __syncthreads();

    // ---- Phase 5: emit remapped packed schedule ---------------------------
    // enc: x-parent c -> c ; plus(s) -> M + 2*pos[s] ; prod(s) -> M + 2*pos[s]+1
    const float NL2E = -1.4426950408889634f;
    for (int i = tid; i < MDIM; i += TPB) {
        short4 p = sP[i];
        int pos = posA[i];
        short4 v;
        int q;
        q = p.x; v.x = (short)(q < MDIM ? q : (q < 2*MDIM ? MDIM + 2*posA[q - MDIM] : MDIM + 2*posA[q - 2*MDIM] + 1));
        q = p.y; v.y = (short)(q < MDIM ? q : (q < 2*MDIM ? MDIM + 2*posA[q - MDIM] : MDIM + 2*posA[q - 2*MDIM] + 1));
        q = p.z; v.z = (short)(q < MDIM ? q : (q < 2*MDIM ? MDIM + 2*posA[q - MDIM] : MDIM + 2*posA[q - 2*MDIM] + 1));
        q = p.w; v.w = (short)(q < MDIM ? q : (q < 2*MDIM ? MDIM + 2*posA[q - MDIM] : MDIM + 2*posA[q - 2*MDIM] + 1));
        sIdx[pos] = v;
        float4 w;
        w.x = W_sig[2*i] * NL2E; w.y = W_sig[2*i + 1] * NL2E; w.z = b_sig[i] * NL2E; w.w = 0.f;
        sWt[pos] = w;
        wepi[pos] = make_float2(w_plus[i], w_prod[i]);
    }
    __syncthreads();                     // last block-wide barrier

    // ---- Main: one warp per row, persistent over groups -------------------
    float*  rb = buf + wid * ROWSTRIDE;          // x at [0,M)
    float2* pp = (float2*)(rb + MDIM);           // interleaved (plus,prod) [M]
    float bias = b_base[0] + b_plus[0] + b_prod[0];

    for (int grp = blockIdx.x; grp < nGroups; grp += gridDim.x) {
        int row = grp * GR + wid;

        // stage x (coalesced float4) and fold x . W_base on the fly
        const float4* xr  = (const float4*)(x + (size_t)row * MDIM);
        const float4* wb4 = (const float4*)W_base;
        float acc = 0.f;
        #pragma unroll
        for (int k = 0; k < MDIM/128; k++) {
            float4 a  = xr[lane + 32*k];
            float4 wv = wb4[lane + 32*k];
            ((float4*)rb)[lane + 32*k] = a;
            acc = fmaf(a.x, wv.x, fmaf(a.y, wv.y, fmaf(a.z, wv.z, fmaf(a.w, wv.w, acc))));
        }
        __syncwarp();

        // level loop: one float2 STS per step, contiguous; next level's
        // schedule prefetched AND unpacked before the syncwarp.
        int s0 = 0;
        int s1 = (int)offs[1];
        int ix, iy, iz, iw; float w0, w1, wz;
        if (lane < s1) {
            short4 q = sIdx[lane]; float4 ww = sWt[lane];
            ix = q.x; iy = q.y; iz = q.z; iw = q.w;
            w0 = ww.x; w1 = ww.y; wz = ww.z;
        }

        for (int L = 0; s0 < MDIM; L++) {
            int s2 = (int)offs[L + 2];
            int n = s1 - s0;
            if (lane < n) {                       // chunk 0 (prefetched)
                float a0 = rb[ix], a1 = rb[iy];
                float b0 = rb[iz], b1 = rb[iw];
                float t  = fmaf(w0, a0, fmaf(w1, a1, wz));
                float2 o2; o2.x = sigmoid_fold(t); o2.y = b0 * b1;
                pp[s0 + lane] = o2;               // single STS.64, contiguous
            }
            for (int cb = s0 + 32; cb < s1; cb += 32) {   // rare wide levels
                int sp = cb + lane;
                if (sp < s1) {
                    short4 q2 = sIdx[sp]; float4 w2 = sWt[sp];
                    float a0 = rb[q2.x], a1 = rb[q2.y];
                    float b0 = rb[q2.z], b1 = rb[q2.w];
                    float t  = fmaf(w2.x, a0, fmaf(w2.y, a1, w2.z));
                    float2 o2; o2.x = sigmoid_fold(t); o2.y = b0 * b1;
                    pp[sp] = o2;
                }
            }
            {   // prefetch + unpack next level chunk 0 (pre-sync, off chain)
                int sp = s1 + lane;
                if (sp < s2) {
                    short4 q = sIdx[sp]; float4 ww = sWt[sp];
                    ix = q.x; iy = q.y; iz = q.z; iw = q.w;
                    w0 = ww.x; w1 = ww.y; wz = ww.z;
                }
            }
            __syncwarp();
            s0 = s1; s1 = s2;
        }

        // epilogue: interleaved pp + permuted weights, one LDS.64 pair per m
        for (int m = lane; m < MDIM; m += 32) {
            float2 pv = pp[m];
            float2 we = wepi[m];
            acc = fmaf(pv.x, we.x, fmaf(pv.y, we.y, acc));
        }
        #pragma unroll
        for (int o = 16; o; o >>= 1) acc += __shfl_xor_sync(0xffffffffu, acc, o);
        if (lane == 0) out[row] = acc + bias;
        __syncwarp();
    }
}

// ---------------------------------------------------------------------------
extern "C" void kernel_launch(void* const* d_in, const int* in_sizes, int n_in,
                              void* d_out, int out_size) {
    const float* x  = (const float*)d_in[0];
    const int*   ri = (const int*)  d_in[1];
    const float* Wb = (const float*)d_in[2];
    const float* bb = (const float*)d_in[3];
    const float* Ws = (const float*)d_in[4];
    const float* bs = (const float*)d_in[5];
    const float* wp = (const float*)d_in[6];
    const float* bp = (const float*)d_in[7];
    const float* wq = (const float*)d_in[8];
    const float* bq = (const float*)d_in[9];
    float* out = (float*)d_out;

    int B = in_sizes[0] / MDIM;          // 8192
    int nGroups = B / GR;                // 512

    static int sm_count = 0;
    if (sm_count == 0) {
        int dev = 0;
        cudaGetDevice(&dev);
        cudaDeviceGetAttribute(&sm_count, cudaDevAttrMultiProcessorCount, dev);
        if (sm_count <= 0) sm_count = 148;
        cudaFuncSetAttribute(tree_kernel,
                             cudaFuncAttributeMaxDynamicSharedMemorySize, SMEM_BYTES);
    }
    int grid = nGroups < sm_count ? nGroups : sm_count;

    tree_kernel<<<grid, TPB, SMEM_BYTES>>>(x, ri, Wb, bb, Ws, bs, wp, bp, wq, bq,
                                           out, nGroups);
}